// round 16
// baseline (speedup 1.0000x reference)
#include <cuda_runtime.h>

#define HH 128
#define WW 128
#define BB 4
#define CIN 64
#define COUT 64
#define OC1 18

// ---------------- scratch (no allocation allowed) ----------------
__device__ __align__(16) float g_xnhwc[BB*HH*WW*CIN];   // x in NHWC (written by conv1)
__device__ __align__(16) float g_off9 [BB*HH*WW*9];     // raw conv1 out, channels 0..8
__device__ __align__(16) float g_wt1p [9*CIN*24];       // conv1 weights [tap][ci][6grp][4] (oc=3g+j, padded)
__device__ __align__(16) float g_wt2  [9*CIN*COUT];     // conv2 weights [k][ci][co]
__device__ float g_stats1[BB*9*2];                      // GN1 sum/sumsq per (b,group)
__device__ float g_stats2[BB*16*2];                     // GN2 sum/sumsq per (b,group)

// ---------------- K: prep weights (+ zero stats) ----------------
__global__ void k_prep_w(const float* __restrict__ w_off, const float* __restrict__ w_dsc) {
    int t = blockIdx.x*blockDim.x + threadIdx.x;
    if (blockIdx.x == 0) {
        if (threadIdx.x < BB*9*2)  g_stats1[threadIdx.x] = 0.f;
        if (threadIdx.x < BB*16*2) g_stats2[threadIdx.x] = 0.f;
    }
    // g_wt1p: [tap][ci][g][4] with oc = 3g+j (j<3), pad j==3
    if (t < 9*CIN*24) {
        int tap = t / (CIN*24); int r = t % (CIN*24);
        int ci = r / 24; int gj = r % 24;
        int g = gj >> 2, j = gj & 3;
        int oc = g*3 + j;
        float v = 0.f;
        if (j < 3 && oc < OC1)
            v = w_off[oc*(CIN*9) + ci*9 + tap];        // w_off (18,64,3,3)
        g_wt1p[t] = v;
    }
    if (t < 9*CIN*COUT) {
        int k = t / (CIN*COUT); int r = t % (CIN*COUT);
        int ci = r / COUT; int co = r % COUT;
        g_wt2[t] = w_dsc[co*(CIN*9) + ci*9 + k];       // w_dsc (64,64,9,1) -> [k][ci][co]
    }
}

// ---------------- K: conv1 3x3 (64->18) + GN1 stats + NHWC emit, ci-split x2 ----------------
// (round-12 proven, unchanged)
__global__ __launch_bounds__(384) void k_conv1(const float* __restrict__ x,
                                               const float* __restrict__ b_off) {
    __shared__ __align__(16) float xs [CIN*132];     // [ci][i], i=0..129 <-> w = i-1
    __shared__ __align__(16) float wsp[3*CIN*24];    // [dx][ci][6grp][4]; reused as reduction buf
    __shared__ float ssum[9], ssq[9];
    int t = threadIdx.x;
    int tx  = t & 31;
    int ty  = t >> 5;        // 0..11
    int ocg = ty >> 1;       // 0..5 (warp-uniform)
    int cih = ty & 1;        // 0/1  (warp-uniform)
    int blk = blockIdx.x;
    int h   = blk & (HH-1);
    int b   = blk >> 7;
    if (t < 9) { ssum[t] = 0.f; ssq[t] = 0.f; }

    float acc[4][3];
    #pragma unroll
    for (int p=0;p<4;p++)
        #pragma unroll
        for (int j=0;j<3;j++) acc[p][j]=0.f;

    const float* xb = x + (size_t)b*CIN*HH*WW;   // NCHW
    int ci0 = cih * 32;

    for (int dy = 0; dy < 3; dy++) {
        int y = h + dy - 1;
        __syncthreads();
        // stage one input row from NCHW: per iter one (ci, 4w) float4, coalesced along w
        for (int idx = t; idx < 64*32; idx += 384) {
            int ci = idx >> 5, j = (idx & 31) << 2;   // w = j..j+3 -> i = j+1..j+4
            float4 v = make_float4(0.f,0.f,0.f,0.f);
            if ((unsigned)y < HH)
                v = *(const float4*)(xb + ((size_t)ci*HH + y)*WW + j);
            int base = ci*132 + j + 1;
            xs[base+0] = v.x;
            xs[base+1] = v.y;
            xs[base+2] = v.z;
            xs[base+3] = v.w;
        }
        if (t < 128) xs[(t & 63)*132 + ((t >> 6) ? 129 : 0)] = 0.f;   // halos (w=-1,128) = 0
        // stage padded weights for this dy's 3 taps: contiguous [dx][ci][24]
        {
            const float4* wsrc = (const float4*)(g_wt1p + dy*3*CIN*24);
            float4* wdst = (float4*)wsp;
            for (int idx = t; idx < 3*CIN*6; idx += 384) wdst[idx] = wsrc[idx];
        }
        __syncthreads();
        // emit NHWC copy of row h (once, data already staged)
        if (dy == 1) {
            for (int idx = t; idx < 128*16; idx += 384) {
                int w = idx >> 4, cq = (idx & 15) << 2;
                float4 v;
                v.x = xs[(cq+0)*132 + w+1];
                v.y = xs[(cq+1)*132 + w+1];
                v.z = xs[(cq+2)*132 + w+1];
                v.w = xs[(cq+3)*132 + w+1];
                *(float4*)(g_xnhwc + (((size_t)b*HH + h)*WW + w)*CIN + cq) = v;
            }
        }
        #pragma unroll 2
        for (int cc = 0; cc < 32; cc++) {
            int ci = ci0 + cc;
            const float4* ap = (const float4*)(xs + ci*132 + tx*4);
            float4 A0 = ap[0], A1 = ap[1];
            float af[8] = {A0.x,A0.y,A0.z,A0.w,A1.x,A1.y,A1.z,A1.w};
            #pragma unroll
            for (int dx = 0; dx < 3; dx++) {
                float4 wv = *(const float4*)(wsp + (dx*CIN + ci)*24 + ocg*4);  // broadcast
                #pragma unroll
                for (int p = 0; p < 4; p++) {
                    float a = af[p+dx];
                    acc[p][0] += a*wv.x;
                    acc[p][1] += a*wv.y;
                    acc[p][2] += a*wv.z;
                }
            }
        }
    }
    __syncthreads();
    // cross-half reduction: half 1 parks in wsp (no longer needed), half 0 accumulates
    float* red = wsp;
    if (cih == 1) {
        int base = (ocg*32 + tx)*12;
        #pragma unroll
        for (int p = 0; p < 4; p++)
            #pragma unroll
            for (int j = 0; j < 3; j++)
                red[base + p*3 + j] = acc[p][j];
    }
    __syncthreads();
    if (cih == 0) {
        int base = (ocg*32 + tx)*12;
        #pragma unroll
        for (int p = 0; p < 4; p++)
            #pragma unroll
            for (int j = 0; j < 3; j++)
                acc[p][j] += red[base + p*3 + j];
        // epilogue: bias, store first 9 channels, GN1 stats (group = oc>>1)
        #pragma unroll
        for (int j = 0; j < 3; j++) {
            int oc = ocg*3 + j;
            float bia = b_off[oc];
            float s = 0.f, sq = 0.f;
            #pragma unroll
            for (int p = 0; p < 4; p++) {
                float r = acc[p][j] + bia;
                s += r; sq += r*r;
                if (oc < 9)
                    g_off9[(((size_t)b*HH + h)*WW + (tx*4 + p))*9 + oc] = r;
            }
            atomicAdd(&ssum[oc>>1], s);
            atomicAdd(&ssq [oc>>1], sq);
        }
    }
    __syncthreads();
    if (t < 9) {
        atomicAdd(&g_stats1[(b*9 + t)*2 + 0], ssum[t]);
        atomicAdd(&g_stats1[(b*9 + t)*2 + 1], ssq[t]);
    }
}

// ---------------- K: main fused, full-row blocks, 4px x 8co micro-tile, occupancy 4 ----------------
// grid: B*H (512), 256 threads: px0=(t&31)*4 (128 px), co0=(t>>5)*8 (64 co)
// 4 blocks/SM (regs capped 64) -> 512/592 = single wave, no quantization
// dynamic smem: S [ci][128px] 32KB | Wc [ci][co] 16KB | cyc 9*128 | sgrp | sc1/sh1
#define SM_S    0
#define SM_WC   32768
#define SM_CYC  49152
#define SM_GRP  53760
#define SM_SC1  53888
#define SM_SH1  53952
#define SM_MAIN 54016

__global__ __launch_bounds__(256, 4) void k_main(const float* __restrict__ b_dsc,
                                                 const float* __restrict__ g_gn_off,
                                                 const float* __restrict__ b_gn_off,
                                                 float* __restrict__ out) {
    extern __shared__ __align__(16) char smem[];
    float* S    = (float*)(smem + SM_S);
    float* Wc   = (float*)(smem + SM_WC);
    float* cyc  = (float*)(smem + SM_CYC);
    float* sgrp = (float*)(smem + SM_GRP);
    float* sc1s = (float*)(smem + SM_SC1);
    float* sh1s = (float*)(smem + SM_SH1);

    int t   = threadIdx.x;
    int blk = blockIdx.x;
    int h   = blk & (HH-1);
    int b   = blk >> 7;

    // inline GN1 finalize (per block, deterministic)
    if (t < 9) {
        int g = t >> 1;
        float N  = 2.f*HH*WW;
        float mu = g_stats1[(b*9+g)*2+0] / N;
        float var= g_stats1[(b*9+g)*2+1] / N - mu*mu;
        float inv= rsqrtf(var + 1e-5f);
        float sc = g_gn_off[t] * inv;
        sc1s[t] = sc;
        sh1s[t] = b_gn_off[t] - mu * sc;
    }
    if (t < 32) sgrp[t] = 0.f;
    __syncthreads();

    // ---- prologue: per-pixel offsets -> tanh -> cumsum -> clipped y coords ----
    if (t < 128) {
        int px = t;
        const float* op = g_off9 + (((size_t)b*HH + h)*WW + px)*9;
        float y[9];
        #pragma unroll
        for (int c = 0; c < 9; c++)
            y[c] = tanhf(op[c]*sc1s[c] + sh1s[c]);
        float o[9];
        o[4]=0.f;
        o[3]=y[3]; o[2]=y[2]+o[3]; o[1]=y[1]+o[2]; o[0]=y[0]+o[1];
        o[5]=y[5]; o[6]=o[5]+y[6]; o[7]=o[6]+y[7]; o[8]=o[7]+y[8];
        #pragma unroll
        for (int k = 0; k < 9; k++)
            cyc[k*128+px] = fminf(fmaxf((float)h + o[k], 0.f), (float)(HH-1));
    }

    int px0 = (t & 31) * 4;
    int co0 = (t >> 5) * 8;
    float acc[4][8];
    #pragma unroll
    for (int p=0;p<4;p++)
        #pragma unroll
        for (int j=0;j<8;j++) acc[p][j]=0.f;

    int spx = t >> 1;            // sampling: one px per 2 threads
    int c32 = (t & 1) * 32;      // each thread: 32 channels
    const float* xb = g_xnhwc + (size_t)b*(HH*WW*CIN);

    for (int k = 0; k < 9; k++) {
        __syncthreads();
        // stage weight chunk [64ci][64co]
        {
            const float4* wsrc = (const float4*)(g_wt2 + k*CIN*COUT);
            float4* wdst = (float4*)Wc;
            #pragma unroll
            for (int i = 0; i < 4; i++)
                wdst[t + i*256] = wsrc[t + i*256];
        }
        // build sample row: vertical 2-point lerp (x-coord is exact integer)
        {
            int x0 = min(max(spx + k - 4, 0), WW-1);
            float ycv = cyc[k*128 + spx];
            float y0f = floorf(ycv);
            float wy  = ycv - y0f;
            int y0 = (int)y0f;
            int y1 = min(y0 + 1, HH-1);
            const float* p0 = xb + ((size_t)y0*WW + x0)*CIN + c32;
            const float* p1 = xb + ((size_t)y1*WW + x0)*CIN + c32;
            #pragma unroll
            for (int q = 0; q < 8; q++) {
                float4 v0 = *(const float4*)(p0 + q*4);
                float4 v1 = *(const float4*)(p1 + q*4);
                int ci = c32 + q*4;
                S[(ci+0)*128 + spx] = v0.x + wy*(v1.x - v0.x);
                S[(ci+1)*128 + spx] = v0.y + wy*(v1.y - v0.y);
                S[(ci+2)*128 + spx] = v0.z + wy*(v1.z - v0.z);
                S[(ci+3)*128 + spx] = v0.w + wy*(v1.w - v0.w);
            }
        }
        __syncthreads();
        // GEMM accumulate: per ci 3 LDS.128 + 32 FFMA
        #pragma unroll 4
        for (int ci = 0; ci < CIN; ci++) {
            float4 av = *(const float4*)(S + ci*128 + px0);
            float4 b0 = *(const float4*)(Wc + ci*COUT + co0);       // broadcast
            float4 b1 = *(const float4*)(Wc + ci*COUT + co0 + 4);   // broadcast
            float a[4] = {av.x, av.y, av.z, av.w};
            #pragma unroll
            for (int p = 0; p < 4; p++) {
                acc[p][0] += a[p]*b0.x; acc[p][1] += a[p]*b0.y;
                acc[p][2] += a[p]*b0.z; acc[p][3] += a[p]*b0.w;
                acc[p][4] += a[p]*b1.x; acc[p][5] += a[p]*b1.y;
                acc[p][6] += a[p]*b1.z; acc[p][7] += a[p]*b1.w;
            }
        }
    }
    __syncthreads();
    // epilogue: bias, float4 stores (4 px per co), GN2 stats (2 groups per thread)
    float s0 = 0.f, q0 = 0.f, s1 = 0.f, q1 = 0.f;
    #pragma unroll
    for (int j = 0; j < 8; j++) {
        int co = co0 + j;
        float bia = b_dsc[co];
        float4 st;
        st.x = acc[0][j] + bia;
        st.y = acc[1][j] + bia;
        st.z = acc[2][j] + bia;
        st.w = acc[3][j] + bia;
        *(float4*)&out[(((size_t)b*COUT + co)*HH + h)*WW + px0] = st;
        float s = st.x + st.y + st.z + st.w;
        float q = st.x*st.x + st.y*st.y + st.z*st.z + st.w*st.w;
        if (j < 4) { s0 += s; q0 += q; } else { s1 += s; q1 += q; }
    }
    int g0 = co0 >> 2;
    atomicAdd(&sgrp[(g0  )*2+0], s0);
    atomicAdd(&sgrp[(g0  )*2+1], q0);
    atomicAdd(&sgrp[(g0+1)*2+0], s1);
    atomicAdd(&sgrp[(g0+1)*2+1], q1);
    __syncthreads();
    if (t < 32) atomicAdd(&g_stats2[b*32 + t], sgrp[t]);
}

// ---------------- K: GN2 finalize + normalize + relu in place, MLP=4 ----------------
// 1024 blocks x 256 threads x 4 float4: each block covers 1/4 of one (b,co) plane
__global__ void k_norm_relu(const float* __restrict__ g_gn, const float* __restrict__ b_gn,
                            float* __restrict__ out) {
    __shared__ float ssc, ssh;
    int blk = blockIdx.x;
    int bc  = blk >> 2;          // b*64 + co  (plane = 4096 float4, block = 1024)
    if (threadIdx.x == 0) {
        int b = bc >> 6, co = bc & 63, g = co >> 2;
        float N  = 4.f*HH*WW;
        float mu = g_stats2[(b*16+g)*2+0] / N;
        float var= g_stats2[(b*16+g)*2+1] / N - mu*mu;
        float inv= rsqrtf(var + 1e-5f);
        float sc = g_gn[co] * inv;
        ssc = sc;
        ssh = b_gn[co] - mu * sc;
    }
    __syncthreads();
    float sc = ssc, sh = ssh;
    float4* o4 = (float4*)out + (size_t)blk*1024 + threadIdx.x;
    float4 v0 = o4[0], v1 = o4[256], v2 = o4[512], v3 = o4[768];
    v0.x = fmaxf(v0.x*sc + sh, 0.f); v0.y = fmaxf(v0.y*sc + sh, 0.f);
    v0.z = fmaxf(v0.z*sc + sh, 0.f); v0.w = fmaxf(v0.w*sc + sh, 0.f);
    v1.x = fmaxf(v1.x*sc + sh, 0.f); v1.y = fmaxf(v1.y*sc + sh, 0.f);
    v1.z = fmaxf(v1.z*sc + sh, 0.f); v1.w = fmaxf(v1.w*sc + sh, 0.f);
    v2.x = fmaxf(v2.x*sc + sh, 0.f); v2.y = fmaxf(v2.y*sc + sh, 0.f);
    v2.z = fmaxf(v2.z*sc + sh, 0.f); v2.w = fmaxf(v2.w*sc + sh, 0.f);
    v3.x = fmaxf(v3.x*sc + sh, 0.f); v3.y = fmaxf(v3.y*sc + sh, 0.f);
    v3.z = fmaxf(v3.z*sc + sh, 0.f); v3.w = fmaxf(v3.w*sc + sh, 0.f);
    o4[0] = v0; o4[256] = v1; o4[512] = v2; o4[768] = v3;
}

// ---------------- launch ----------------
extern "C" void kernel_launch(void* const* d_in, const int* in_sizes, int n_in,
                              void* d_out, int out_size) {
    const float* x        = (const float*)d_in[0];
    const float* w_off    = (const float*)d_in[1];
    const float* b_off    = (const float*)d_in[2];
    const float* g_gn_off = (const float*)d_in[3];
    const float* b_gn_off = (const float*)d_in[4];
    const float* w_dsc    = (const float*)d_in[5];
    const float* b_dsc    = (const float*)d_in[6];
    const float* g_gn     = (const float*)d_in[7];
    const float* b_gn     = (const float*)d_in[8];
    float* out = (float*)d_out;

    cudaFuncSetAttribute(k_main, cudaFuncAttributeMaxDynamicSharedMemorySize, SM_MAIN);

    k_prep_w<<<144,256>>>(w_off, w_dsc);
    k_conv1<<<BB*HH, 384>>>(x, b_off);
    k_main<<<BB*HH, 256, SM_MAIN>>>(b_dsc, g_gn_off, b_gn_off, out);
    k_norm_relu<<<1024,256>>>(g_gn, b_gn, out);
}

// round 17
// speedup vs baseline: 1.2767x; 1.2767x over previous
#include <cuda_runtime.h>

#define HH 128
#define WW 128
#define BB 4
#define CIN 64
#define COUT 64
#define OC1 18

// ---------------- scratch (no allocation allowed) ----------------
__device__ __align__(16) float g_xnhwc[BB*HH*WW*CIN];   // x in NHWC (written by conv1)
__device__ __align__(16) float g_off9 [BB*HH*WW*9];     // raw conv1 out, channels 0..8
__device__ __align__(16) float g_wt1p [9*CIN*24];       // conv1 weights [tap][ci][6grp][4] (oc=3g+j, padded)
__device__ __align__(16) float g_wt2  [9*CIN*COUT];     // conv2 weights [k][ci][co]
__device__ float g_stats1[BB*9*2];                      // GN1 sum/sumsq per (b,group)
__device__ float g_stats2[BB*16*2];                     // GN2 sum/sumsq per (b,group)

// ---------------- K: prep weights (+ zero stats) ----------------
__global__ void k_prep_w(const float* __restrict__ w_off, const float* __restrict__ w_dsc) {
    int t = blockIdx.x*blockDim.x + threadIdx.x;
    if (blockIdx.x == 0) {
        if (threadIdx.x < BB*9*2)  g_stats1[threadIdx.x] = 0.f;
        if (threadIdx.x < BB*16*2) g_stats2[threadIdx.x] = 0.f;
    }
    // g_wt1p: [tap][ci][g][4] with oc = 3g+j (j<3), pad j==3
    if (t < 9*CIN*24) {
        int tap = t / (CIN*24); int r = t % (CIN*24);
        int ci = r / 24; int gj = r % 24;
        int g = gj >> 2, j = gj & 3;
        int oc = g*3 + j;
        float v = 0.f;
        if (j < 3 && oc < OC1)
            v = w_off[oc*(CIN*9) + ci*9 + tap];        // w_off (18,64,3,3)
        g_wt1p[t] = v;
    }
    if (t < 9*CIN*COUT) {
        int k = t / (CIN*COUT); int r = t % (CIN*COUT);
        int ci = r / COUT; int co = r % COUT;
        g_wt2[t] = w_dsc[co*(CIN*9) + ci*9 + k];       // w_dsc (64,64,9,1) -> [k][ci][co]
    }
}

// ---------------- K: conv1 3x3 (64->18) + GN1 stats + NHWC emit, ci-split x2 ----------------
// (round-12 proven, unchanged)
__global__ __launch_bounds__(384) void k_conv1(const float* __restrict__ x,
                                               const float* __restrict__ b_off) {
    __shared__ __align__(16) float xs [CIN*132];     // [ci][i], i=0..129 <-> w = i-1
    __shared__ __align__(16) float wsp[3*CIN*24];    // [dx][ci][6grp][4]; reused as reduction buf
    __shared__ float ssum[9], ssq[9];
    int t = threadIdx.x;
    int tx  = t & 31;
    int ty  = t >> 5;        // 0..11
    int ocg = ty >> 1;       // 0..5 (warp-uniform)
    int cih = ty & 1;        // 0/1  (warp-uniform)
    int blk = blockIdx.x;
    int h   = blk & (HH-1);
    int b   = blk >> 7;
    if (t < 9) { ssum[t] = 0.f; ssq[t] = 0.f; }

    float acc[4][3];
    #pragma unroll
    for (int p=0;p<4;p++)
        #pragma unroll
        for (int j=0;j<3;j++) acc[p][j]=0.f;

    const float* xb = x + (size_t)b*CIN*HH*WW;   // NCHW
    int ci0 = cih * 32;

    for (int dy = 0; dy < 3; dy++) {
        int y = h + dy - 1;
        __syncthreads();
        // stage one input row from NCHW: per iter one (ci, 4w) float4, coalesced along w
        for (int idx = t; idx < 64*32; idx += 384) {
            int ci = idx >> 5, j = (idx & 31) << 2;   // w = j..j+3 -> i = j+1..j+4
            float4 v = make_float4(0.f,0.f,0.f,0.f);
            if ((unsigned)y < HH)
                v = *(const float4*)(xb + ((size_t)ci*HH + y)*WW + j);
            int base = ci*132 + j + 1;
            xs[base+0] = v.x;
            xs[base+1] = v.y;
            xs[base+2] = v.z;
            xs[base+3] = v.w;
        }
        if (t < 128) xs[(t & 63)*132 + ((t >> 6) ? 129 : 0)] = 0.f;   // halos (w=-1,128) = 0
        // stage padded weights for this dy's 3 taps: contiguous [dx][ci][24]
        {
            const float4* wsrc = (const float4*)(g_wt1p + dy*3*CIN*24);
            float4* wdst = (float4*)wsp;
            for (int idx = t; idx < 3*CIN*6; idx += 384) wdst[idx] = wsrc[idx];
        }
        __syncthreads();
        // emit NHWC copy of row h (once, data already staged)
        if (dy == 1) {
            for (int idx = t; idx < 128*16; idx += 384) {
                int w = idx >> 4, cq = (idx & 15) << 2;
                float4 v;
                v.x = xs[(cq+0)*132 + w+1];
                v.y = xs[(cq+1)*132 + w+1];
                v.z = xs[(cq+2)*132 + w+1];
                v.w = xs[(cq+3)*132 + w+1];
                *(float4*)(g_xnhwc + (((size_t)b*HH + h)*WW + w)*CIN + cq) = v;
            }
        }
        #pragma unroll 2
        for (int cc = 0; cc < 32; cc++) {
            int ci = ci0 + cc;
            const float4* ap = (const float4*)(xs + ci*132 + tx*4);
            float4 A0 = ap[0], A1 = ap[1];
            float af[8] = {A0.x,A0.y,A0.z,A0.w,A1.x,A1.y,A1.z,A1.w};
            #pragma unroll
            for (int dx = 0; dx < 3; dx++) {
                float4 wv = *(const float4*)(wsp + (dx*CIN + ci)*24 + ocg*4);  // broadcast
                #pragma unroll
                for (int p = 0; p < 4; p++) {
                    float a = af[p+dx];
                    acc[p][0] += a*wv.x;
                    acc[p][1] += a*wv.y;
                    acc[p][2] += a*wv.z;
                }
            }
        }
    }
    __syncthreads();
    // cross-half reduction: half 1 parks in wsp (no longer needed), half 0 accumulates
    float* red = wsp;
    if (cih == 1) {
        int base = (ocg*32 + tx)*12;
        #pragma unroll
        for (int p = 0; p < 4; p++)
            #pragma unroll
            for (int j = 0; j < 3; j++)
                red[base + p*3 + j] = acc[p][j];
    }
    __syncthreads();
    if (cih == 0) {
        int base = (ocg*32 + tx)*12;
        #pragma unroll
        for (int p = 0; p < 4; p++)
            #pragma unroll
            for (int j = 0; j < 3; j++)
                acc[p][j] += red[base + p*3 + j];
        // epilogue: bias, store first 9 channels, GN1 stats (group = oc>>1)
        #pragma unroll
        for (int j = 0; j < 3; j++) {
            int oc = ocg*3 + j;
            float bia = b_off[oc];
            float s = 0.f, sq = 0.f;
            #pragma unroll
            for (int p = 0; p < 4; p++) {
                float r = acc[p][j] + bia;
                s += r; sq += r*r;
                if (oc < 9)
                    g_off9[(((size_t)b*HH + h)*WW + (tx*4 + p))*9 + oc] = r;
            }
            atomicAdd(&ssum[oc>>1], s);
            atomicAdd(&ssq [oc>>1], sq);
        }
    }
    __syncthreads();
    if (t < 9) {
        atomicAdd(&g_stats1[(b*9 + t)*2 + 0], ssum[t]);
        atomicAdd(&g_stats1[(b*9 + t)*2 + 1], ssq[t]);
    }
}

// ---------------- K: main fused (round-12 proven body; S-fill conflict fix) ----------------
// grid: B*H*2 (64-px half-rows), 256 threads: 16x16, 4px x 4co micro-tile
__global__ __launch_bounds__(256) void k_main(const float* __restrict__ b_dsc,
                                              const float* __restrict__ g_gn_off,
                                              const float* __restrict__ b_gn_off,
                                              float* __restrict__ out) {
    __shared__ __align__(16) float S [CIN*68];    // samples [ci][px(68 pad)]
    __shared__ __align__(16) float Wc[CIN*COUT];  // weight chunk [ci][co]
    __shared__ int   cy0[9*64];
    __shared__ float cwy[9*64];
    __shared__ float sgrp[32];
    __shared__ float sc1s[9], sh1s[9];

    int t    = threadIdx.x;
    int blk  = blockIdx.x;
    int half = blk & 1;
    int h    = (blk >> 1) & (HH-1);
    int b    = blk >> 8;
    int w0   = half * 64;

    // inline GN1 finalize (per block, deterministic)
    if (t < 9) {
        int g = t >> 1;
        float N  = 2.f*HH*WW;
        float mu = g_stats1[(b*9+g)*2+0] / N;
        float var= g_stats1[(b*9+g)*2+1] / N - mu*mu;
        float inv= rsqrtf(var + 1e-5f);
        float sc = g_gn_off[t] * inv;
        sc1s[t] = sc;
        sh1s[t] = b_gn_off[t] - mu * sc;
    }
    if (t < 32) sgrp[t] = 0.f;
    __syncthreads();

    // ---- prologue: per-pixel offsets -> tanh -> cumsum -> coords ----
    if (t < 64) {
        int px = t;
        int w  = w0 + px;
        const float* op = g_off9 + (((size_t)b*HH + h)*WW + w)*9;
        float y[9];
        #pragma unroll
        for (int c = 0; c < 9; c++)
            y[c] = tanhf(op[c]*sc1s[c] + sh1s[c]);
        float o[9];
        o[4]=0.f;
        o[3]=y[3]; o[2]=y[2]+o[3]; o[1]=y[1]+o[2]; o[0]=y[0]+o[1];
        o[5]=y[5]; o[6]=o[5]+y[6]; o[7]=o[6]+y[7]; o[8]=o[7]+y[8];
        #pragma unroll
        for (int k = 0; k < 9; k++) {
            float yc  = fminf(fmaxf((float)h + o[k], 0.f), (float)(HH-1));
            float y0f = floorf(yc);
            cy0[k*64+px] = (int)y0f;
            cwy[k*64+px] = yc - y0f;
        }
    }

    int tx = t & 15, ty = t >> 4;
    float acc[4][4];
    #pragma unroll
    for (int i=0;i<4;i++)
        #pragma unroll
        for (int j=0;j<4;j++) acc[i][j]=0.f;

    int spx = t >> 2;            // sampling: one px per 4 threads
    int c4  = (t & 3) * 4;       // ci = c4 + q*16 (2-way STS banks vs 4-way with *16)
    const float* xb = g_xnhwc + (size_t)b*(HH*WW*CIN);

    for (int k = 0; k < 9; k++) {
        __syncthreads();
        // stage weight chunk [64ci][64co] (coalesced, pre-transposed)
        {
            const float4* wsrc = (const float4*)(g_wt2 + k*CIN*COUT);
            float4* wdst = (float4*)Wc;
            #pragma unroll
            for (int i = 0; i < 4; i++)
                wdst[t + i*256] = wsrc[t + i*256];
        }
        // build sample chunk: vertical 2-point lerp (x-coord is exact integer)
        {
            int w  = w0 + spx;
            int x0 = min(max(w + k - 4, 0), WW-1);
            int y0 = cy0[k*64 + spx];
            float wy = cwy[k*64 + spx];
            int y1 = min(y0 + 1, HH-1);
            const float* p0 = xb + ((size_t)y0*WW + x0)*CIN + c4;
            const float* p1 = xb + ((size_t)y1*WW + x0)*CIN + c4;
            #pragma unroll
            for (int q = 0; q < 4; q++) {
                float4 v0 = *(const float4*)(p0 + q*16);
                float4 v1 = *(const float4*)(p1 + q*16);
                int ci = c4 + q*16;
                S[(ci+0)*68 + spx] = v0.x + wy*(v1.x - v0.x);
                S[(ci+1)*68 + spx] = v0.y + wy*(v1.y - v0.y);
                S[(ci+2)*68 + spx] = v0.z + wy*(v1.z - v0.z);
                S[(ci+3)*68 + spx] = v0.w + wy*(v1.w - v0.w);
            }
        }
        __syncthreads();
        // SGEMM accumulate over this 64-ci chunk: 2 LDS.128 + 16 FFMA per ci
        #pragma unroll 2
        for (int ci = 0; ci < CIN; ci++) {
            float4 av = *(const float4*)(S + ci*68 + ty*4);     // broadcast
            float4 bb = *(const float4*)(Wc + ci*COUT + tx*4);
            acc[0][0]+=av.x*bb.x; acc[0][1]+=av.x*bb.y; acc[0][2]+=av.x*bb.z; acc[0][3]+=av.x*bb.w;
            acc[1][0]+=av.y*bb.x; acc[1][1]+=av.y*bb.y; acc[1][2]+=av.y*bb.z; acc[1][3]+=av.y*bb.w;
            acc[2][0]+=av.z*bb.x; acc[2][1]+=av.z*bb.y; acc[2][2]+=av.z*bb.z; acc[2][3]+=av.z*bb.w;
            acc[3][0]+=av.w*bb.x; acc[3][1]+=av.w*bb.y; acc[3][2]+=av.w*bb.z; acc[3][3]+=av.w*bb.w;
        }
    }
    __syncthreads();
    // epilogue: bias, raw store (NCHW), GN2 stats (co group == tx)
    float4 bia = *(const float4*)(b_dsc + tx*4);
    float s = 0.f, sq = 0.f;
    #pragma unroll
    for (int i = 0; i < 4; i++) {
        int w = w0 + ty*4 + i;
        float r0 = acc[i][0] + bia.x;
        float r1 = acc[i][1] + bia.y;
        float r2 = acc[i][2] + bia.z;
        float r3 = acc[i][3] + bia.w;
        out[(((size_t)b*COUT + tx*4+0)*HH + h)*WW + w] = r0;
        out[(((size_t)b*COUT + tx*4+1)*HH + h)*WW + w] = r1;
        out[(((size_t)b*COUT + tx*4+2)*HH + h)*WW + w] = r2;
        out[(((size_t)b*COUT + tx*4+3)*HH + h)*WW + w] = r3;
        s  += r0+r1+r2+r3;
        sq += r0*r0 + r1*r1 + r2*r2 + r3*r3;
    }
    atomicAdd(&sgrp[tx*2+0], s);
    atomicAdd(&sgrp[tx*2+1], sq);
    __syncthreads();
    if (t < 32) atomicAdd(&g_stats2[b*32 + t], sgrp[t]);
}

// ---------------- K: GN2 finalize + normalize + relu in place ----------------
// 4096 blocks x 256 threads x float4: each block covers 1/16 of one (b,co) plane
__global__ void k_norm_relu(const float* __restrict__ g_gn, const float* __restrict__ b_gn,
                            float* __restrict__ out) {
    __shared__ float ssc, ssh;
    int blk = blockIdx.x;
    int bc  = blk >> 4;          // b*64 + co
    if (threadIdx.x == 0) {
        int b = bc >> 6, co = bc & 63, g = co >> 2;
        float N  = 4.f*HH*WW;
        float mu = g_stats2[(b*16+g)*2+0] / N;
        float var= g_stats2[(b*16+g)*2+1] / N - mu*mu;
        float inv= rsqrtf(var + 1e-5f);
        float sc = g_gn[co] * inv;
        ssc = sc;
        ssh = b_gn[co] - mu * sc;
    }
    __syncthreads();
    float sc = ssc, sh = ssh;
    int idx = blk*256 + threadIdx.x;   // float4 index
    float4 v = ((float4*)out)[idx];
    v.x = fmaxf(v.x*sc + sh, 0.f);
    v.y = fmaxf(v.y*sc + sh, 0.f);
    v.z = fmaxf(v.z*sc + sh, 0.f);
    v.w = fmaxf(v.w*sc + sh, 0.f);
    ((float4*)out)[idx] = v;
}

// ---------------- launch ----------------
extern "C" void kernel_launch(void* const* d_in, const int* in_sizes, int n_in,
                              void* d_out, int out_size) {
    const float* x        = (const float*)d_in[0];
    const float* w_off    = (const float*)d_in[1];
    const float* b_off    = (const float*)d_in[2];
    const float* g_gn_off = (const float*)d_in[3];
    const float* b_gn_off = (const float*)d_in[4];
    const float* w_dsc    = (const float*)d_in[5];
    const float* b_dsc    = (const float*)d_in[6];
    const float* g_gn     = (const float*)d_in[7];
    const float* b_gn     = (const float*)d_in[8];
    float* out = (float*)d_out;

    k_prep_w<<<144,256>>>(w_off, w_dsc);
    k_conv1<<<BB*HH, 384>>>(x, b_off);
    k_main<<<BB*HH*2, 256>>>(b_dsc, g_gn_off, b_gn_off, out);
    k_norm_relu<<<4096,256>>>(g_gn, b_gn, out);
}